// round 10
// baseline (speedup 1.0000x reference)
#include <cuda_runtime.h>
#include <cuda_bf16.h>

#define THREADS 512
#define VT      128000
#define VS      32000
#define KSEL    256
#define MAXB    2048
#define MAXROWS 2048

// global scratch (static __device__ arrays are the sanctioned scratch path)
__device__ uint2 g_cand[MAXROWS][MAXB];
__device__ int   g_cnt[MAXROWS];          // zero-initialized; B resets after use

// monotone float->uint key
__device__ __forceinline__ unsigned f2k(float x) {
    unsigned u = __float_as_uint(x);
    return (u & 0x80000000u) ? ~u : (u | 0x80000000u);
}
__device__ __forceinline__ float k2f(unsigned k) {
    unsigned u = (k & 0x80000000u) ? (k & 0x7fffffffu) : ~k;
    return __uint_as_float(u);
}

// ======================= Kernel A: pure streaming scan =======================
__global__ void __launch_bounds__(THREADS, 4)
scan_kernel(const float* __restrict__ logits, float* __restrict__ out) {
    const int bid  = blockIdx.x;
    const int row  = bid >> 1;
    const int half = bid & 1;
    const int tid  = threadIdx.x;

    const float4* __restrict__ rp =
        (const float4*)(logits + (size_t)row * VT) + (size_t)half * (VT / 8);
    const unsigned idx0 = (unsigned)half * (VT / 2);

    // zero own output half-row
    {
        float4 z = make_float4(0.f, 0.f, 0.f, 0.f);
        float4* op = (float4*)(out + (size_t)row * VS) + (size_t)half * (VS / 8);
        for (int i = tid; i < VS / 8; i += THREADS) op[i] = z;
    }

    const float thrVal = 2.45f;           // E[candidates] ~ 915/row for N(0,1)
    int* cnt = &g_cnt[row];
    // 64000 floats per CTA = 4000 chunks of 16
    for (int i = tid; i < VT / 32; i += THREADS) {
        const float4 a = rp[4 * i + 0];
        const float4 b = rp[4 * i + 1];
        const float4 c = rp[4 * i + 2];
        const float4 d = rp[4 * i + 3];
        float m0 = fmaxf(fmaxf(a.x, a.y), fmaxf(a.z, a.w));
        float m1 = fmaxf(fmaxf(b.x, b.y), fmaxf(b.z, b.w));
        float m2 = fmaxf(fmaxf(c.x, c.y), fmaxf(c.z, c.w));
        float m3 = fmaxf(fmaxf(d.x, d.y), fmaxf(d.z, d.w));
        if (fmaxf(fmaxf(m0, m1), fmaxf(m2, m3)) >= thrVal) {
            const float v[16] = {a.x,a.y,a.z,a.w, b.x,b.y,b.z,b.w,
                                 c.x,c.y,c.z,c.w, d.x,d.y,d.z,d.w};
#pragma unroll
            for (int j = 0; j < 16; j++) {
                if (v[j] >= thrVal) {
                    int p = atomicAdd(cnt, 1);
                    if (p < MAXB)
                        g_cand[row][p] = make_uint2(f2k(v[j]), idx0 + i * 16 + j);
                }
            }
        }
    }
}

// ==================== Kernel B: exact top-K select + scatter =================
__global__ void __launch_bounds__(THREADS, 4)
select_kernel(const float* __restrict__ logits,
              const void* __restrict__ mapping,
              float* __restrict__ out) {
    __shared__ unsigned h256[256];
    __shared__ unsigned tKey[2][MAXB], tIdx[2][MAXB];
    __shared__ float    fred[THREADS];
    __shared__ float    fred2[THREADS];
    __shared__ unsigned selKey[KSEL], selIdx[KSEL];
    __shared__ int      s_bin;
    __shared__ unsigned s_above;
    __shared__ int      nCand, selCount, nNext, s_is64;
    __shared__ unsigned s_maxkey, s_minkey;
    __shared__ float    s_mean, s_std, s_denom;

    const int tid = threadIdx.x;
    const int row = blockIdx.x;
    const float* __restrict__ rowf = logits + (size_t)row * VT;
    float* __restrict__ orow = out + (size_t)row * VS;

    if (tid == 0) {
        const unsigned* m32 = (const unsigned*)mapping;
        int all0 = 1;
        for (int i = 1; i < 64; i += 2)
            if (m32[i] != 0u) { all0 = 0; break; }
        s_is64 = all0;
        s_denom = 0.0f;
        selCount = 0;
        s_maxkey = 0u;
        s_minkey = 0xFFFFFFFFu;
        nCand = g_cnt[row];
    }
    __syncthreads();

    int nc = nCand;
    if (nc >= KSEL && nc <= MAXB) {
        // ---- common path: load candidates from global scratch ----
        unsigned lmax = 0u, lmin = 0xFFFFFFFFu;
        for (int p = tid; p < nc; p += THREADS) {
            uint2 e = g_cand[row][p];
            tKey[0][p] = e.x;
            tIdx[0][p] = e.y;
            lmax = max(lmax, e.x);
            lmin = min(lmin, e.x);
        }
#pragma unroll
        for (int off = 16; off > 0; off >>= 1) {
            lmax = max(lmax, __shfl_xor_sync(0xffffffffu, lmax, off));
            lmin = min(lmin, __shfl_xor_sync(0xffffffffu, lmin, off));
        }
        if ((tid & 31) == 0) {
            atomicMax(&s_maxkey, lmax);
            atomicMin(&s_minkey, lmin);
        }
        __syncthreads();
    } else {
        // ---- fallback (arbitrary input distributions): rescan row ----
        const float4* __restrict__ rp = (const float4*)rowf;
        float thrVal = 2.45f;
        float stdGuess = 1.0f;
        bool haveStats = false;
        for (int attempt = 0; attempt < 12; attempt++) {
            // sampled stats once
            if (!haveStats) {
                float x = rowf[tid * (VT / THREADS)];
                fred[tid] = x;
                fred2[tid] = x * x;
                __syncthreads();
                for (int s = THREADS / 2; s > 0; s >>= 1) {
                    if (tid < s) {
                        fred[tid] += fred[tid + s];
                        fred2[tid] += fred2[tid + s];
                    }
                    __syncthreads();
                }
                if (tid == 0) {
                    float mean = fred[0] * (1.0f / THREADS);
                    float var  = fred2[0] * (1.0f / THREADS) - mean * mean;
                    s_mean = mean;
                    s_std  = sqrtf(fmaxf(var, 1e-12f));
                }
                __syncthreads();
                stdGuess = s_std;
                float cand = s_mean + 2.45f * s_std;
                if (fabsf(cand - thrVal) < 0.05f * s_std)
                    cand += (nc < KSEL) ? -0.60f * s_std : 0.35f * s_std;
                thrVal = cand;
                haveStats = true;
            }
            if (tid == 0) { nCand = 0; s_maxkey = 0u; s_minkey = 0xFFFFFFFFu; }
            __syncthreads();
            for (int i = tid; i < VT / 16; i += THREADS) {
                const float4 a = rp[4 * i + 0];
                const float4 b = rp[4 * i + 1];
                const float4 c = rp[4 * i + 2];
                const float4 d = rp[4 * i + 3];
                float m0 = fmaxf(fmaxf(a.x, a.y), fmaxf(a.z, a.w));
                float m1 = fmaxf(fmaxf(b.x, b.y), fmaxf(b.z, b.w));
                float m2 = fmaxf(fmaxf(c.x, c.y), fmaxf(c.z, c.w));
                float m3 = fmaxf(fmaxf(d.x, d.y), fmaxf(d.z, d.w));
                if (fmaxf(fmaxf(m0, m1), fmaxf(m2, m3)) >= thrVal) {
                    const float v[16] = {a.x,a.y,a.z,a.w, b.x,b.y,b.z,b.w,
                                         c.x,c.y,c.z,c.w, d.x,d.y,d.z,d.w};
#pragma unroll
                    for (int j = 0; j < 16; j++) {
                        if (v[j] >= thrVal) {
                            unsigned key = f2k(v[j]);
                            int p = atomicAdd(&nCand, 1);
                            if (p < MAXB) {
                                tKey[0][p] = key;
                                tIdx[0][p] = (unsigned)(i * 16 + j);
                                atomicMax(&s_maxkey, key);
                                atomicMin(&s_minkey, key);
                            }
                        }
                    }
                }
            }
            __syncthreads();
            nc = nCand;
            if (nc >= KSEL && nc <= MAXB) break;
            if (nc < KSEL) thrVal -= 0.60f * stdGuess + 1e-6f;
            else           thrVal += 0.35f * stdGuess + 1e-6f;
            __syncthreads();
        }
    }

    // ---- exact top-KSEL: byte-radix select from highest differing byte ----
    int cur = 0;
    int curN = nc < MAXB ? nc : MAXB;
    int need = KSEL;
    const unsigned keyxor = s_minkey ^ s_maxkey;
    int level_start = (keyxor == 0u) ? -1 : (3 - (__clz(keyxor) >> 3));
    __syncthreads();

    for (int level = level_start; level >= 0 && need > 0; level--) {
        if (curN == need) {
            for (int p = tid; p < curN; p += THREADS) {
                int q = atomicAdd(&selCount, 1);
                selKey[q] = tKey[cur][p]; selIdx[q] = tIdx[cur][p];
            }
            need = 0;
            __syncthreads();
            break;
        }
        if (tid < 256) h256[tid] = 0u;
        __syncthreads();
        const int sh = level * 8;
        for (int p = tid; p < curN; p += THREADS)
            atomicAdd(&h256[(tKey[cur][p] >> sh) & 0xFFu], 1u);
        __syncthreads();
        if (tid < 32) {
            unsigned local[8];
            unsigned part = 0;
#pragma unroll
            for (int j = 0; j < 8; j++) {
                local[j] = h256[255 - (tid * 8 + j)];
                part += local[j];
            }
            unsigned incl = part;
#pragma unroll
            for (int off = 1; off < 32; off <<= 1) {
                unsigned v = __shfl_up_sync(0xffffffffu, incl, off);
                if (tid >= off) incl += v;
            }
            unsigned before = incl - part;
            if (before < (unsigned)need && incl >= (unsigned)need) {
                unsigned cum = before;
#pragma unroll
                for (int j = 0; j < 8; j++) {
                    unsigned cj = local[j];
                    if (cum + cj >= (unsigned)need) {
                        s_bin = 255 - (tid * 8 + j);
                        s_above = cum;
                        break;
                    }
                    cum += cj;
                }
            }
        }
        if (tid == 0) nNext = 0;
        __syncthreads();
        const int c = s_bin;
        const int G = (int)s_above;
        const int oth = cur ^ 1;
        for (int p = tid; p < curN; p += THREADS) {
            unsigned key = tKey[cur][p];
            int byte = (int)((key >> sh) & 0xFFu);
            if (byte > c) {
                int q = atomicAdd(&selCount, 1);
                selKey[q] = key; selIdx[q] = tIdx[cur][p];
            } else if (byte == c) {
                int q = atomicAdd(&nNext, 1);
                tKey[oth][q] = key; tIdx[oth][q] = tIdx[cur][p];
            }
        }
        __syncthreads();
        need -= G;
        curN = nNext;
        cur = oth;
        __syncthreads();
    }

    // identical keys remain; take `need` smallest indices
    if (need > 0) {
        for (int p = tid; p < curN; p += THREADS) {
            unsigned my = tIdx[cur][p];
            int rank = 0;
            for (int j = 0; j < curN; j++) rank += (tIdx[cur][j] < my);
            if (rank < need) {
                int q = atomicAdd(&selCount, 1);
                selKey[q] = tKey[cur][p]; selIdx[q] = my;
            }
        }
        __syncthreads();
    }

    const float vmax = k2f(s_maxkey);

    // ---- weights + denominator ----
    float w = 0.0f;
    if (tid < KSEL) {
        w = exp2f((k2f(selKey[tid]) - vmax) * 0.36067376022224085f); // 1/(4 ln2)
        float ws = w;
#pragma unroll
        for (int off = 16; off > 0; off >>= 1)
            ws += __shfl_xor_sync(0xffffffffu, ws, off);
        if ((tid & 31) == 0) atomicAdd(&s_denom, ws);
    }
    __syncthreads();
    const float inv = 1.0f / s_denom;

    // ---- scatter (row pre-zeroed by kernel A) ----
    if (tid < KSEL) {
        unsigned idx = selIdx[tid];
        int sid;
        if (s_is64) sid = (int)((const long long*)mapping)[idx];
        else        sid = ((const int*)mapping)[idx];
        atomicAdd(&orow[sid], w * inv);
    }

    // ---- reset counter for next graph replay ----
    if (tid == 0) g_cnt[row] = 0;
}

extern "C" void kernel_launch(void* const* d_in, const int* in_sizes, int n_in,
                              void* d_out, int out_size) {
    const float* logits  = (const float*)d_in[0];
    const void*  mapping = d_in[1];
    float* out = (float*)d_out;
    int rows = in_sizes[0] / VT;   // B*T = 2048
    scan_kernel<<<rows * 2, THREADS>>>(logits, out);
    select_kernel<<<rows, THREADS>>>(logits, mapping, out);
}

// round 11
// speedup vs baseline: 1.7861x; 1.7861x over previous
#include <cuda_runtime.h>
#include <cuda_bf16.h>
#include <cstdint>

#define THREADS 512
#define VT      128000
#define VS      32000
#define KSEL    256
#define MAXB    2048
#define TILE_F4    1000          // 4000 floats = 16000 bytes per tile
#define TILE_BYTES 16000
#define NTILES     32            // 32 * 16000 B = 512000 B = one row

struct __align__(128) Smem {
    float4   buf[2][TILE_F4];            // 32000 B double buffer
    unsigned tKey[2][MAXB];
    unsigned tIdx[2][MAXB];
    unsigned long long mbar[2];
    unsigned selKey[KSEL], selIdx[KSEL];
    float    fred[THREADS], fred2[THREADS];
    int      s_bin; unsigned s_above;
    int      nCand, selCount, nNext, s_is64;
    unsigned s_maxkey, s_minkey;
    float    s_mean, s_std, s_denom;
};

// monotone float->uint key
__device__ __forceinline__ unsigned f2k(float x) {
    unsigned u = __float_as_uint(x);
    return (u & 0x80000000u) ? ~u : (u | 0x80000000u);
}
__device__ __forceinline__ float k2f(unsigned k) {
    unsigned u = (k & 0x80000000u) ? (k & 0x7fffffffu) : ~k;
    return __uint_as_float(u);
}

__device__ __forceinline__ unsigned s2u(const void* p) {
    unsigned a;
    asm("{ .reg .u64 t; cvta.to.shared.u64 t, %1; cvt.u32.u64 %0, t; }"
        : "=r"(a) : "l"(p));
    return a;
}
__device__ __forceinline__ void mbar_init(unsigned a, unsigned cnt) {
    asm volatile("mbarrier.init.shared.b64 [%0], %1;" :: "r"(a), "r"(cnt) : "memory");
}
__device__ __forceinline__ void mbar_expect(unsigned a, unsigned bytes) {
    asm volatile("mbarrier.arrive.expect_tx.shared.b64 _, [%0], %1;"
                 :: "r"(a), "r"(bytes) : "memory");
}
__device__ __forceinline__ void bulk_g2s(unsigned dst, const void* src,
                                         unsigned bytes, unsigned mbar) {
    asm volatile("cp.async.bulk.shared::cta.global.mbarrier::complete_tx::bytes "
                 "[%0], [%1], %2, [%3];"
                 :: "r"(dst), "l"(src), "r"(bytes), "r"(mbar) : "memory");
}
__device__ __forceinline__ void mbar_wait(unsigned a, unsigned parity) {
    unsigned done;
    asm volatile(
        "{\n\t.reg .pred p;\n\t"
        "mbarrier.try_wait.parity.acquire.cta.shared::cta.b64 p, [%1], %2;\n\t"
        "selp.b32 %0, 1, 0, p;\n\t}"
        : "=r"(done) : "r"(a), "r"(parity) : "memory");
    if (!done) {
        asm volatile(
            "{\n\t.reg .pred P1;\n\t"
            "WL%=:\n\t"
            "mbarrier.try_wait.parity.acquire.cta.shared::cta.b64 P1, [%0], %1, 0x989680;\n\t"
            "@P1 bra.uni WD%=;\n\t"
            "bra.uni WL%=;\n\t"
            "WD%=:\n\t}"
            :: "r"(a), "r"(parity) : "memory");
    }
}

extern __shared__ char smem_raw[];

__global__ void __launch_bounds__(THREADS)
vocab_project_kernel(const float* __restrict__ logits,
                     const void* __restrict__ mapping,
                     float* __restrict__ out) {
    Smem* sm = (Smem*)smem_raw;
    const int tid = threadIdx.x;
    const int row = blockIdx.x;
    const float* __restrict__ rowf = logits + (size_t)row * VT;
    const char*  rowb = (const char*)rowf;
    float* __restrict__ orow = out + (size_t)row * VS;

    const unsigned mb0 = s2u(&sm->mbar[0]);
    const unsigned mb1 = s2u(&sm->mbar[1]);
    const unsigned bu0 = s2u(&sm->buf[0][0]);
    const unsigned bu1 = s2u(&sm->buf[1][0]);

    if (tid == 0) {
        const unsigned* m32 = (const unsigned*)mapping;
        int all0 = 1;
        for (int i = 1; i < 64; i += 2)
            if (m32[i] != 0u) { all0 = 0; break; }
        sm->s_is64 = all0;
        sm->s_denom = 0.0f;
        sm->selCount = 0;
        mbar_init(mb0, 1);
        mbar_init(mb1, 1);
    }
    __syncthreads();

    // ---- streamed collection via bulk-async double buffer ----
    int ph0 = 0, ph1 = 0;           // per-buffer mbarrier phase (persists across retries)
    float thrVal = 2.45f;           // E[count] ~ 915 for N(0,1)
    float stdGuess = 1.0f;
    bool haveStats = false;
    for (int attempt = 0; attempt < 10; attempt++) {
        if (tid == 0) { sm->nCand = 0; sm->s_maxkey = 0u; sm->s_minkey = 0xFFFFFFFFu; }
        __syncthreads();
        if (tid == 0) {
            mbar_expect(mb0, TILE_BYTES);
            bulk_g2s(bu0, rowb + 0 * TILE_BYTES, TILE_BYTES, mb0);
            mbar_expect(mb1, TILE_BYTES);
            bulk_g2s(bu1, rowb + 1 * TILE_BYTES, TILE_BYTES, mb1);
        }
        for (int k = 0; k < NTILES; k++) {
            const int b = k & 1;
            if (b == 0) { mbar_wait(mb0, ph0); ph0 ^= 1; }
            else        { mbar_wait(mb1, ph1); ph1 ^= 1; }
            const float4* tb = sm->buf[b];
            const unsigned base = (unsigned)k * (TILE_F4 * 4);
            for (int i = tid; i < TILE_F4; i += THREADS) {
                float4 v = tb[i];
                float m = fmaxf(fmaxf(v.x, v.y), fmaxf(v.z, v.w));
                if (m >= thrVal) {
                    float a4[4] = {v.x, v.y, v.z, v.w};
#pragma unroll
                    for (int j = 0; j < 4; j++) {
                        if (a4[j] >= thrVal) {
                            unsigned key = f2k(a4[j]);
                            int p = atomicAdd(&sm->nCand, 1);
                            if (p < MAXB) {
                                sm->tKey[0][p] = key;
                                sm->tIdx[0][p] = base + i * 4 + j;
                                atomicMax(&sm->s_maxkey, key);
                                atomicMin(&sm->s_minkey, key);
                            }
                        }
                    }
                }
            }
            __syncthreads();            // everyone done reading buf b
            const int nk = k + 2;
            if (nk < NTILES && tid == 0) {
                const unsigned mb = b ? mb1 : mb0;
                const unsigned bu = b ? bu1 : bu0;
                mbar_expect(mb, TILE_BYTES);
                bulk_g2s(bu, rowb + (size_t)nk * TILE_BYTES, TILE_BYTES, mb);
            }
        }
        __syncthreads();
        int nc = sm->nCand;
        if (nc >= KSEL && nc <= MAXB) break;
        // rare fallback: sampled stats, adjust threshold, re-stream
        if (!haveStats) {
            float x = rowf[tid * (VT / THREADS)];
            sm->fred[tid] = x;
            sm->fred2[tid] = x * x;
            __syncthreads();
            for (int s = THREADS / 2; s > 0; s >>= 1) {
                if (tid < s) {
                    sm->fred[tid] += sm->fred[tid + s];
                    sm->fred2[tid] += sm->fred2[tid + s];
                }
                __syncthreads();
            }
            if (tid == 0) {
                float mean = sm->fred[0] * (1.0f / THREADS);
                float var  = sm->fred2[0] * (1.0f / THREADS) - mean * mean;
                sm->s_mean = mean;
                sm->s_std  = sqrtf(fmaxf(var, 1e-12f));
            }
            __syncthreads();
            stdGuess = sm->s_std;
            float cand = sm->s_mean + 2.45f * sm->s_std;
            if (fabsf(cand - thrVal) < 0.05f * sm->s_std)
                cand += (nc < KSEL) ? -0.60f * sm->s_std : 0.35f * sm->s_std;
            thrVal = cand;
            haveStats = true;
        } else {
            if (nc < KSEL) thrVal -= 0.60f * stdGuess + 1e-6f;
            else           thrVal += 0.35f * stdGuess + 1e-6f;
        }
        __syncthreads();
    }

    // ---- zero own output row ----
    {
        float4 z = make_float4(0.f, 0.f, 0.f, 0.f);
        float4* op = (float4*)orow;
        for (int i = tid; i < VS / 4; i += THREADS) op[i] = z;
    }

    // ---- exact top-KSEL: byte-radix select from highest differing byte ----
    int cur = 0;
    int curN = sm->nCand < MAXB ? sm->nCand : MAXB;
    int need = KSEL;
    const unsigned keyxor = sm->s_minkey ^ sm->s_maxkey;
    int level_start = (keyxor == 0u) ? -1 : (3 - (__clz(keyxor) >> 3));
    unsigned* h256 = sm->tKey[1] + MAXB - 256;  // reuse tail of unused ping buffer? NO — conflicts.
    __syncthreads();

    // dedicated small histogram in fred storage (reuse float buffer as uint)
    unsigned* hist = (unsigned*)sm->fred;       // 256 x 4B fits in fred[512]

    for (int level = level_start; level >= 0 && need > 0; level--) {
        if (curN == need) {
            for (int p = tid; p < curN; p += THREADS) {
                int q = atomicAdd(&sm->selCount, 1);
                sm->selKey[q] = sm->tKey[cur][p];
                sm->selIdx[q] = sm->tIdx[cur][p];
            }
            need = 0;
            __syncthreads();
            break;
        }
        if (tid < 256) hist[tid] = 0u;
        __syncthreads();
        const int sh = level * 8;
        for (int p = tid; p < curN; p += THREADS)
            atomicAdd(&hist[(sm->tKey[cur][p] >> sh) & 0xFFu], 1u);
        __syncthreads();
        if (tid < 32) {
            unsigned local[8];
            unsigned part = 0;
#pragma unroll
            for (int j = 0; j < 8; j++) {
                local[j] = hist[255 - (tid * 8 + j)];
                part += local[j];
            }
            unsigned incl = part;
#pragma unroll
            for (int off = 1; off < 32; off <<= 1) {
                unsigned v = __shfl_up_sync(0xffffffffu, incl, off);
                if (tid >= off) incl += v;
            }
            unsigned before = incl - part;
            if (before < (unsigned)need && incl >= (unsigned)need) {
                unsigned cum = before;
#pragma unroll
                for (int j = 0; j < 8; j++) {
                    unsigned cj = local[j];
                    if (cum + cj >= (unsigned)need) {
                        sm->s_bin = 255 - (tid * 8 + j);
                        sm->s_above = cum;
                        break;
                    }
                    cum += cj;
                }
            }
        }
        if (tid == 0) sm->nNext = 0;
        __syncthreads();
        const int c = sm->s_bin;
        const int G = (int)sm->s_above;
        const int oth = cur ^ 1;
        for (int p = tid; p < curN; p += THREADS) {
            unsigned key = sm->tKey[cur][p];
            int byte = (int)((key >> sh) & 0xFFu);
            if (byte > c) {
                int q = atomicAdd(&sm->selCount, 1);
                sm->selKey[q] = key; sm->selIdx[q] = sm->tIdx[cur][p];
            } else if (byte == c) {
                int q = atomicAdd(&sm->nNext, 1);
                sm->tKey[oth][q] = key; sm->tIdx[oth][q] = sm->tIdx[cur][p];
            }
        }
        __syncthreads();
        need -= G;
        curN = sm->nNext;
        cur = oth;
        __syncthreads();
    }

    // identical keys remain; take `need` smallest indices
    if (need > 0) {
        for (int p = tid; p < curN; p += THREADS) {
            unsigned my = sm->tIdx[cur][p];
            int rank = 0;
            for (int j = 0; j < curN; j++) rank += (sm->tIdx[cur][j] < my);
            if (rank < need) {
                int q = atomicAdd(&sm->selCount, 1);
                sm->selKey[q] = sm->tKey[cur][p];
                sm->selIdx[q] = my;
            }
        }
        __syncthreads();
    }

    const float vmax = k2f(sm->s_maxkey);

    // ---- weights + denominator ----
    float w = 0.0f;
    if (tid < KSEL) {
        w = exp2f((k2f(sm->selKey[tid]) - vmax) * 0.36067376022224085f); // 1/(4 ln2)
        float ws = w;
#pragma unroll
        for (int off = 16; off > 0; off >>= 1)
            ws += __shfl_xor_sync(0xffffffffu, ws, off);
        if ((tid & 31) == 0) atomicAdd(&sm->s_denom, ws);
    }
    __syncthreads();
    const float inv = 1.0f / sm->s_denom;

    // ---- scatter ----
    if (tid < KSEL) {
        unsigned idx = sm->selIdx[tid];
        int sid;
        if (sm->s_is64) sid = (int)((const long long*)mapping)[idx];
        else            sid = ((const int*)mapping)[idx];
        atomicAdd(&orow[sid], w * inv);
    }
}

extern "C" void kernel_launch(void* const* d_in, const int* in_sizes, int n_in,
                              void* d_out, int out_size) {
    const float* logits  = (const float*)d_in[0];
    const void*  mapping = d_in[1];
    float* out = (float*)d_out;
    int rows = in_sizes[0] / VT;   // B*T = 2048
    int shbytes = (int)sizeof(Smem);
    cudaFuncSetAttribute(vocab_project_kernel,
                         cudaFuncAttributeMaxDynamicSharedMemorySize, shbytes);
    vocab_project_kernel<<<rows, THREADS, shbytes>>>(logits, mapping, out);
}